// round 3
// baseline (speedup 1.0000x reference)
#include <cuda_runtime.h>
#include <cuda_bf16.h>

#define N_NODES 50000
#define N_EDGES 800000
#define E2      850000   // edges + self loops
#define IN_F    128
#define HID     64
#define BN_EPS  1e-5f
#define INV_N   (1.0 / (double)N_NODES)

// ---------------- scratch (device globals; no allocation allowed) ----------------
__device__ int    g_is64;
__device__ int    g_deg[N_NODES];
__device__ int    g_fill[N_NODES];
__device__ float  g_dinv[N_NODES];
__device__ int    g_rowptr[N_NODES + 1];
__device__ int2   g_cw[E2];                 // {col, weight-bits} interleaved
__device__ float  g_hA[N_NODES * HID];
__device__ float  g_hB[N_NODES * HID];
__device__ float  g_h0[N_NODES * HID];
__device__ double g_sum[4][HID];
__device__ double g_sq[4][HID];

// ---------------- init: deg=1, fill=0, zero stats, detect edge dtype ----------------
__global__ void init_kernel(const int* __restrict__ e) {
    int n = blockIdx.x * blockDim.x + threadIdx.x;
    if (n < N_NODES) { g_deg[n] = 1; g_fill[n] = 0; }
    if (blockIdx.x == 0) {
        int t = threadIdx.x;
        if (t < 4 * HID) { ((double*)g_sum)[t] = 0.0; ((double*)g_sq)[t] = 0.0; }
        if (t < 32) {
            // int64 little-endian with values < 50000 -> odd 32-bit words all zero
            int nz = 0;
            #pragma unroll
            for (int i = 0; i < 4; i++) nz += (e[2 * (t * 4 + i) + 1] != 0);
            unsigned any = __any_sync(0xffffffffu, nz != 0);
            if (t == 0) g_is64 = any ? 0 : 1;
        }
    }
}

__device__ __forceinline__ int fetch_idx(const void* ei, long long pos) {
    int v;
    if (g_is64) v = (int)((const long long*)ei)[pos];
    else        v = ((const int*)ei)[pos];
    return min(max(v, 0), N_NODES - 1);   // crash insurance
}

__global__ void count_deg_kernel(const void* __restrict__ ei) {
    int e = blockIdx.x * blockDim.x + threadIdx.x;
    if (e < N_EDGES) atomicAdd(&g_deg[fetch_idx(ei, (long long)N_EDGES + e)], 1);
}

// single-block exclusive prefix sum over degrees; also writes dinv
__global__ void scan_kernel() {
    __shared__ int buf[1024];
    const int CH = (N_NODES + 1023) / 1024;  // 49
    int t = threadIdx.x;
    int beg = t * CH;
    int end = min(beg + CH, N_NODES);
    int local = 0;
    for (int i = beg; i < end; i++) {
        int d = g_deg[i];
        g_dinv[i] = rsqrtf((float)d);
        local += d;
    }
    buf[t] = local;
    __syncthreads();
    for (int off = 1; off < 1024; off <<= 1) {
        int add = (t >= off) ? buf[t - off] : 0;
        __syncthreads();
        buf[t] += add;
        __syncthreads();
    }
    int run = buf[t] - local;
    for (int i = beg; i < end; i++) { g_rowptr[i] = run; run += g_deg[i]; }
    if (t == 1023) g_rowptr[N_NODES] = buf[1023];
}

__global__ void fill_csr_kernel(const void* __restrict__ ei) {
    int e = blockIdx.x * blockDim.x + threadIdx.x;
    if (e >= E2) return;
    int s, d;
    if (e < N_EDGES) {
        s = fetch_idx(ei, e);
        d = fetch_idx(ei, (long long)N_EDGES + e);
    } else {
        s = e - N_EDGES; d = s;
    }
    int pos = g_rowptr[d] + atomicAdd(&g_fill[d], 1);
    g_cw[pos] = make_int2(s, __float_as_int(g_dinv[s] * g_dinv[d]));
}

// ---------------- SpMM: warp per node; optional fused BN-stats epilogue ----------------
// hout[n] = wacc * sum_e w*hin[col] (+bias) (+wh0*h0[n]); STATS: accumulate sum/sumsq
template <bool STATS>
__global__ __launch_bounds__(256) void spmm_kernel(
    const float* __restrict__ hin, float* __restrict__ hout,
    const float* __restrict__ bias, const float* __restrict__ h0p,
    float wacc, float wh0, int set)
{
    __shared__ float ssum[HID], ssq[HID];
    if (STATS) {
        if (threadIdx.x < HID) { ssum[threadIdx.x] = 0.f; ssq[threadIdx.x] = 0.f; }
        __syncthreads();
    }
    int node = blockIdx.x * 8 + (threadIdx.x >> 5);
    int lane = threadIdx.x & 31;
    const float2* __restrict__ hin2 = (const float2*)hin;
    int beg = g_rowptr[node];
    int end = g_rowptr[node + 1];
    float2 a0 = make_float2(0.f, 0.f), a1 = a0, a2 = a0, a3 = a0;
    int e = beg;
    for (; e + 3 < end; e += 4) {
        int2 cw0 = g_cw[e],   cw1 = g_cw[e+1], cw2 = g_cw[e+2], cw3 = g_cw[e+3];
        float2 v0 = hin2[cw0.x*32 + lane];
        float2 v1 = hin2[cw1.x*32 + lane];
        float2 v2 = hin2[cw2.x*32 + lane];
        float2 v3 = hin2[cw3.x*32 + lane];
        float w0 = __int_as_float(cw0.y), w1 = __int_as_float(cw1.y);
        float w2 = __int_as_float(cw2.y), w3 = __int_as_float(cw3.y);
        a0.x += w0*v0.x; a0.y += w0*v0.y;
        a1.x += w1*v1.x; a1.y += w1*v1.y;
        a2.x += w2*v2.x; a2.y += w2*v2.y;
        a3.x += w3*v3.x; a3.y += w3*v3.y;
    }
    for (; e < end; e++) {
        int2 cw = g_cw[e];
        float w = __int_as_float(cw.y);
        float2 v = hin2[cw.x*32 + lane];
        a0.x += w*v.x; a0.y += w*v.y;
    }
    float2 r;
    r.x = ((a0.x + a1.x) + (a2.x + a3.x)) * wacc;
    r.y = ((a0.y + a1.y) + (a2.y + a3.y)) * wacc;
    if (bias) {
        float2 b = ((const float2*)bias)[lane];
        r.x += b.x; r.y += b.y;
    }
    if (h0p) {
        float2 z = ((const float2*)h0p)[node*32 + lane];
        r.x += wh0 * z.x; r.y += wh0 * z.y;
    }
    ((float2*)hout)[node*32 + lane] = r;
    if (STATS) {
        atomicAdd(&ssum[2*lane],     r.x);
        atomicAdd(&ssum[2*lane + 1], r.y);
        atomicAdd(&ssq[2*lane],      r.x * r.x);
        atomicAdd(&ssq[2*lane + 1],  r.y * r.y);
        __syncthreads();
        int t = threadIdx.x;
        if (t < HID)            atomicAdd(&g_sum[set][t], (double)ssum[t]);
        else if (t < 2 * HID)   atomicAdd(&g_sq[set][t - HID], (double)ssq[t - HID]);
    }
}

// ---------------- dense GEMM with optional fused BN(+ReLU) on the input ----------------
// C[N,64] = act(A)[N,KIN] @ W[KIN,64] (+bias); act = BN(scale,shift)+ReLU when BNSET>=0
template <int KIN, int BNSET>
__global__ __launch_bounds__(256) void gemm_kernel(
    const float* __restrict__ A, const float* __restrict__ W,
    const float* __restrict__ bias, float* __restrict__ C,
    const float* __restrict__ gam, const float* __restrict__ bet)
{
    __shared__ float Ws[KIN * 64];
    __shared__ float As[32 * KIN];
    __shared__ float sc[HID], sh[HID];
    int tid = threadIdx.x;
    if (BNSET >= 0 && tid < HID) {
        double mean = g_sum[BNSET][tid] * INV_N;
        double var  = g_sq[BNSET][tid] * INV_N - mean * mean;
        float s = gam[tid] * rsqrtf((float)var + BN_EPS);
        sc[tid] = s;
        sh[tid] = bet[tid] - (float)mean * s;
    }
    for (int i = tid; i < KIN * 64; i += 256) Ws[i] = W[i];
    if (BNSET >= 0) __syncthreads();   // sc/sh ready before A-load uses them
    int base = blockIdx.x * 32;
    for (int i = tid; i < 32 * KIN; i += 256) {
        int r = i / KIN, c = i - r * KIN;
        float v = (base + r < N_NODES) ? A[(base + r) * KIN + c] : 0.f;
        if (BNSET >= 0) v = fmaxf(fmaf(v, sc[c], sh[c]), 0.f);
        As[i] = v;
    }
    __syncthreads();
    int f  = tid & 63;
    int ig = tid >> 6;
    float acc[8];
#pragma unroll
    for (int i = 0; i < 8; i++) acc[i] = 0.f;
#pragma unroll 8
    for (int k = 0; k < KIN; k++) {
        float wv = Ws[k * 64 + f];
#pragma unroll
        for (int i = 0; i < 8; i++)
            acc[i] += As[(ig * 8 + i) * KIN + k] * wv;
    }
    float bv = bias ? bias[f] : 0.f;
#pragma unroll
    for (int i = 0; i < 8; i++) {
        int n = base + ig * 8 + i;
        if (n < N_NODES) C[n * 64 + f] = acc[i] + bv;
    }
}

// ---------------- layer-4 BN apply (inline finalize) -> writes h and h0 ----------------
__global__ __launch_bounds__(256) void bn_apply_final_kernel(
    float* __restrict__ h, float* __restrict__ h0,
    const float* __restrict__ gam, const float* __restrict__ bet)
{
    __shared__ float sc[HID], sh[HID];
    int tid = threadIdx.x;
    if (tid < HID) {
        double mean = g_sum[3][tid] * INV_N;
        double var  = g_sq[3][tid] * INV_N - mean * mean;
        float s = gam[tid] * rsqrtf((float)var + BN_EPS);
        sc[tid] = s;
        sh[tid] = bet[tid] - (float)mean * s;
    }
    __syncthreads();
    int i = blockIdx.x * blockDim.x + tid;
    if (i >= N_NODES * (HID / 4)) return;
    float4 v = ((const float4*)h)[i];
    int f = (i * 4) & (HID - 1);
    v.x = fmaxf(fmaf(v.x, sc[f],     sh[f]),     0.f);
    v.y = fmaxf(fmaf(v.y, sc[f + 1], sh[f + 1]), 0.f);
    v.z = fmaxf(fmaf(v.z, sc[f + 2], sh[f + 2]), 0.f);
    v.w = fmaxf(fmaf(v.w, sc[f + 3], sh[f + 3]), 0.f);
    ((float4*)h)[i]  = v;
    ((float4*)h0)[i] = v;
}

// ---------------- fused FC + log-softmax: out = log_softmax(A @ Wfc + bfc) ----------------
__global__ __launch_bounds__(256) void fc_logsoftmax_kernel(
    const float* __restrict__ A, const float* __restrict__ W,
    const float* __restrict__ bias, float* __restrict__ out)
{
    __shared__ float Ws[64 * 64];
    __shared__ float As[32 * 64];
    __shared__ float L[32][65];
    int tid = threadIdx.x;
    for (int i = tid; i < 64 * 64; i += 256) Ws[i] = W[i];
    int base = blockIdx.x * 32;
    for (int i = tid; i < 32 * 64; i += 256) {
        int r = i >> 6, c = i & 63;
        As[i] = (base + r < N_NODES) ? A[(base + r) * 64 + c] : 0.f;
    }
    __syncthreads();
    int f  = tid & 63;
    int ig = tid >> 6;
    float acc[8];
#pragma unroll
    for (int i = 0; i < 8; i++) acc[i] = 0.f;
#pragma unroll 8
    for (int k = 0; k < 64; k++) {
        float wv = Ws[k * 64 + f];
#pragma unroll
        for (int i = 0; i < 8; i++)
            acc[i] += As[(ig * 8 + i) * 64 + k] * wv;
    }
    float bv = bias[f];
#pragma unroll
    for (int i = 0; i < 8; i++) L[ig * 8 + i][f] = acc[i] + bv;
    __syncthreads();
    // log-softmax: each warp handles 4 rows; 32 lanes cover 64 classes (2 each)
    int w = tid >> 5, lane = tid & 31;
#pragma unroll
    for (int j = 0; j < 4; j++) {
        int r = w * 4 + j;
        int node = base + r;
        if (node >= N_NODES) break;
        float v0 = L[r][lane], v1 = L[r][lane + 32];
        float m = fmaxf(v0, v1);
        for (int o = 16; o; o >>= 1) m = fmaxf(m, __shfl_xor_sync(0xffffffffu, m, o));
        float s = __expf(v0 - m) + __expf(v1 - m);
        for (int o = 16; o; o >>= 1) s += __shfl_xor_sync(0xffffffffu, s, o);
        float ls = m + __logf(s);
        out[node * 64 + lane]      = v0 - ls;
        out[node * 64 + lane + 32] = v1 - ls;
    }
}

// ---------------- host ----------------
extern "C" void kernel_launch(void* const* d_in, const int* in_sizes, int n_in,
                              void* d_out, int out_size) {
    const float* x   = (const float*)d_in[0];
    const void*  ei  = d_in[1];            // int32 or int64, detected on device
    const float* W1  = (const float*)d_in[2];
    const float* b1  = (const float*)d_in[3];
    const float* W2  = (const float*)d_in[4];
    const float* b2  = (const float*)d_in[5];
    const float* Wx  = (const float*)d_in[6];   // [2,64,64]
    const float* bx  = (const float*)d_in[7];   // [2,64]
    const float* g1  = (const float*)d_in[8];
    const float* be1 = (const float*)d_in[9];
    const float* g2  = (const float*)d_in[10];
    const float* be2 = (const float*)d_in[11];
    const float* g3  = (const float*)d_in[12];
    const float* be3 = (const float*)d_in[13];
    const float* Wfc = (const float*)d_in[14];
    const float* bfc = (const float*)d_in[15];
    float* out = (float*)d_out;

    float *hA, *hB, *h0;
    cudaGetSymbolAddress((void**)&hA, g_hA);
    cudaGetSymbolAddress((void**)&hB, g_hB);
    cudaGetSymbolAddress((void**)&h0, g_h0);

    // ---- build normalized CSR (by dst) ----
    init_kernel<<<(N_NODES + 255) / 256, 256>>>((const int*)ei);
    count_deg_kernel<<<(N_EDGES + 255) / 256, 256>>>(ei);
    scan_kernel<<<1, 1024>>>();
    fill_csr_kernel<<<(E2 + 255) / 256, 256>>>(ei);

    const int GEMM_GRID = (N_NODES + 31) / 32;   // 1563
    const int SPMM_GRID = N_NODES / 8;           // 6250

    // ---- layer 1 (IN_F=128, no BN on input) ----
    gemm_kernel<128, -1><<<GEMM_GRID, 256>>>(x, W1, nullptr, hB, nullptr, nullptr);
    spmm_kernel<true><<<SPMM_GRID, 256>>>(hB, hA, b1, nullptr, 1.f, 0.f, 0);
    // ---- layer 2 (BN set 0 fused into GEMM input) ----
    gemm_kernel<64, 0><<<GEMM_GRID, 256>>>(hA, W2, nullptr, hB, g1, be1);
    spmm_kernel<true><<<SPMM_GRID, 256>>>(hB, hA, b2, nullptr, 1.f, 0.f, 1);
    // ---- extra layer 0 (BN set 1) ----
    gemm_kernel<64, 1><<<GEMM_GRID, 256>>>(hA, Wx, nullptr, hB, g2, be2);
    spmm_kernel<true><<<SPMM_GRID, 256>>>(hB, hA, bx, nullptr, 1.f, 0.f, 2);
    // ---- extra layer 1 (BN set 2) ----
    gemm_kernel<64, 2><<<GEMM_GRID, 256>>>(hA, Wx + 64 * 64, nullptr, hB, g3, be3);
    spmm_kernel<true><<<SPMM_GRID, 256>>>(hB, hA, bx + 64, nullptr, 1.f, 0.f, 3);
    // ---- final BN apply (set 3) -> hA normalized, h0 copy ----
    bn_apply_final_kernel<<<(N_NODES * (HID / 4) + 255) / 256, 256>>>(hA, h0, g3, be3);

    // ---- APPNP: 10 steps, ping-pong hA <-> hB ----
    float* cur = hA;
    float* nxt = hB;
    for (int it = 0; it < 10; it++) {
        spmm_kernel<false><<<SPMM_GRID, 256>>>(cur, nxt, nullptr, h0, 0.9f, 0.1f, 0);
        float* t = cur; cur = nxt; nxt = t;
    }
    // result in hA

    // ---- head: FC + log_softmax fused ----
    fc_logsoftmax_kernel<<<GEMM_GRID, 256>>>(cur, Wfc, bfc, out);
}

// round 4
// speedup vs baseline: 1.1383x; 1.1383x over previous
#include <cuda_runtime.h>
#include <cuda_bf16.h>

#define N_NODES 50000
#define N_EDGES 800000
#define E2      850000   // edges + self loops
#define IN_F    128
#define HID     64
#define BN_EPS  1e-5f
#define INV_N   (1.0 / (double)N_NODES)

// ---------------- scratch (device globals; no allocation allowed) ----------------
__device__ int    g_is64;
__device__ int    g_deg[N_NODES];
__device__ int    g_fill[N_NODES];
__device__ float  g_dinv[N_NODES];
__device__ int    g_rowptr[N_NODES + 1];
__device__ __align__(16) int2 g_cw[E2 + 2];   // {col, weight-bits}; padded for int4 tail
__device__ float  g_hA[N_NODES * HID];
__device__ float  g_hB[N_NODES * HID];
__device__ float  g_h0[N_NODES * HID];
__device__ double g_sum[4][HID];
__device__ double g_sq[4][HID];

// ---------------- init: deg=1, fill=0, zero stats, detect edge dtype ----------------
__global__ void init_kernel(const int* __restrict__ e) {
    int n = blockIdx.x * blockDim.x + threadIdx.x;
    if (n < N_NODES) { g_deg[n] = 1; g_fill[n] = 0; }
    if (blockIdx.x == 0) {
        int t = threadIdx.x;
        if (t < 4 * HID) { ((double*)g_sum)[t] = 0.0; ((double*)g_sq)[t] = 0.0; }
        if (t < 32) {
            // int64 little-endian with values < 50000 -> odd 32-bit words all zero
            int nz = 0;
            #pragma unroll
            for (int i = 0; i < 4; i++) nz += (e[2 * (t * 4 + i) + 1] != 0);
            unsigned any = __any_sync(0xffffffffu, nz != 0);
            if (t == 0) g_is64 = any ? 0 : 1;
        }
    }
}

__device__ __forceinline__ int fetch_idx(const void* ei, long long pos) {
    int v;
    if (g_is64) v = (int)((const long long*)ei)[pos];
    else        v = ((const int*)ei)[pos];
    return min(max(v, 0), N_NODES - 1);   // crash insurance
}

__global__ void count_deg_kernel(const void* __restrict__ ei) {
    int e = blockIdx.x * blockDim.x + threadIdx.x;
    if (e < N_EDGES) atomicAdd(&g_deg[fetch_idx(ei, (long long)N_EDGES + e)], 1);
}

// single-block exclusive prefix sum over degrees; also writes dinv
__global__ void scan_kernel() {
    __shared__ int buf[1024];
    const int CH = (N_NODES + 1023) / 1024;  // 49
    int t = threadIdx.x;
    int beg = t * CH;
    int end = min(beg + CH, N_NODES);
    int local = 0;
    for (int i = beg; i < end; i++) {
        int d = g_deg[i];
        g_dinv[i] = rsqrtf((float)d);
        local += d;
    }
    buf[t] = local;
    __syncthreads();
    for (int off = 1; off < 1024; off <<= 1) {
        int add = (t >= off) ? buf[t - off] : 0;
        __syncthreads();
        buf[t] += add;
        __syncthreads();
    }
    int run = buf[t] - local;
    for (int i = beg; i < end; i++) { g_rowptr[i] = run; run += g_deg[i]; }
    if (t == 1023) g_rowptr[N_NODES] = buf[1023];
}

__global__ void fill_csr_kernel(const void* __restrict__ ei) {
    int e = blockIdx.x * blockDim.x + threadIdx.x;
    if (e >= E2) return;
    int s, d;
    if (e < N_EDGES) {
        s = fetch_idx(ei, e);
        d = fetch_idx(ei, (long long)N_EDGES + e);
    } else {
        s = e - N_EDGES; d = s;
    }
    int pos = g_rowptr[d] + atomicAdd(&g_fill[d], 1);
    g_cw[pos] = make_int2(s, __float_as_int(g_dinv[s] * g_dinv[d]));
}

// ---------------- SpMM: warp per node, int4 edge metadata, float2 per lane ----------------
// hout[n] = wacc * sum_e w*hin[col] (+bias) (+wh0*h0[n])
__global__ __launch_bounds__(256) void spmm_kernel(
    const float* __restrict__ hin, float* __restrict__ hout,
    const float* __restrict__ bias, const float* __restrict__ h0p,
    float wacc, float wh0)
{
    int node = blockIdx.x * 8 + (threadIdx.x >> 5);
    int lane = threadIdx.x & 31;
    const float2* __restrict__ hin2 = (const float2*)hin;
    const int4*   __restrict__ cw4  = (const int4*)g_cw;
    int beg = g_rowptr[node];
    int end = g_rowptr[node + 1];
    float2 a0 = make_float2(0.f, 0.f), a1 = a0, a2 = a0, a3 = a0;
    int e = beg;
    if ((e & 1) && e < end) {               // peel to 16B alignment
        int2 cw = g_cw[e];
        float w = __int_as_float(cw.y);
        float2 v = hin2[cw.x*32 + lane];
        a0.x += w*v.x; a0.y += w*v.y;
        e++;
    }
    for (; e + 3 < end; e += 4) {
        int4 q0 = cw4[e >> 1];
        int4 q1 = cw4[(e >> 1) + 1];
        float2 v0 = hin2[q0.x*32 + lane];
        float2 v1 = hin2[q0.z*32 + lane];
        float2 v2 = hin2[q1.x*32 + lane];
        float2 v3 = hin2[q1.z*32 + lane];
        float w0 = __int_as_float(q0.y), w1 = __int_as_float(q0.w);
        float w2 = __int_as_float(q1.y), w3 = __int_as_float(q1.w);
        a0.x += w0*v0.x; a0.y += w0*v0.y;
        a1.x += w1*v1.x; a1.y += w1*v1.y;
        a2.x += w2*v2.x; a2.y += w2*v2.y;
        a3.x += w3*v3.x; a3.y += w3*v3.y;
    }
    for (; e < end; e++) {
        int2 cw = g_cw[e];
        float w = __int_as_float(cw.y);
        float2 v = hin2[cw.x*32 + lane];
        a0.x += w*v.x; a0.y += w*v.y;
    }
    float2 r;
    r.x = ((a0.x + a1.x) + (a2.x + a3.x)) * wacc;
    r.y = ((a0.y + a1.y) + (a2.y + a3.y)) * wacc;
    if (bias) {
        float2 b = ((const float2*)bias)[lane];
        r.x += b.x; r.y += b.y;
    }
    if (h0p) {
        float2 z = ((const float2*)h0p)[node*32 + lane];
        r.x += wh0 * z.x; r.y += wh0 * z.y;
    }
    ((float2*)hout)[node*32 + lane] = r;
}

// ---------------- BN stats: 256 blocks, float partials, 16k double atomics ----------------
__global__ __launch_bounds__(256) void bn_stats_kernel(const float* __restrict__ h, int set) {
    int f   = threadIdx.x & 63;
    int grp = threadIdx.x >> 6;  // 0..3
    float s = 0.f, q = 0.f;
    for (int n = blockIdx.x * 4 + grp; n < N_NODES; n += gridDim.x * 4) {
        float v = h[n * HID + f];
        s += v; q += v * v;
    }
    __shared__ float ss[4][HID], qq[4][HID];
    ss[grp][f] = s; qq[grp][f] = q;
    __syncthreads();
    if (grp == 0) {
        s = (ss[0][f] + ss[1][f]) + (ss[2][f] + ss[3][f]);
        q = (qq[0][f] + qq[1][f]) + (qq[2][f] + qq[3][f]);
        atomicAdd(&g_sum[set][f], (double)s);
        atomicAdd(&g_sq[set][f],  (double)q);
    }
}

// ---------------- dense GEMM with optional fused BN(+ReLU) on the input ----------------
// C[N,64] = act(A)[N,KIN] @ W[KIN,64] (+bias); act = BN(scale,shift)+ReLU when BNSET>=0
template <int KIN, int BNSET>
__global__ __launch_bounds__(256) void gemm_kernel(
    const float* __restrict__ A, const float* __restrict__ W,
    const float* __restrict__ bias, float* __restrict__ C,
    const float* __restrict__ gam, const float* __restrict__ bet)
{
    __shared__ float Ws[KIN * 64];
    __shared__ float As[32 * KIN];
    __shared__ float sc[HID], sh[HID];
    int tid = threadIdx.x;
    if (BNSET >= 0 && tid < HID) {
        double mean = g_sum[BNSET][tid] * INV_N;
        double var  = g_sq[BNSET][tid] * INV_N - mean * mean;
        float s = gam[tid] * rsqrtf((float)var + BN_EPS);
        sc[tid] = s;
        sh[tid] = bet[tid] - (float)mean * s;
    }
    for (int i = tid; i < KIN * 64; i += 256) Ws[i] = W[i];
    if (BNSET >= 0) __syncthreads();   // sc/sh ready before A-load uses them
    int base = blockIdx.x * 32;
    for (int i = tid; i < 32 * KIN; i += 256) {
        int r = i / KIN, c = i - r * KIN;
        float v = (base + r < N_NODES) ? A[(base + r) * KIN + c] : 0.f;
        if (BNSET >= 0) v = fmaxf(fmaf(v, sc[c], sh[c]), 0.f);
        As[i] = v;
    }
    __syncthreads();
    int f  = tid & 63;
    int ig = tid >> 6;
    float acc[8];
#pragma unroll
    for (int i = 0; i < 8; i++) acc[i] = 0.f;
#pragma unroll 8
    for (int k = 0; k < KIN; k++) {
        float wv = Ws[k * 64 + f];
#pragma unroll
        for (int i = 0; i < 8; i++)
            acc[i] += As[(ig * 8 + i) * KIN + k] * wv;
    }
    float bv = bias ? bias[f] : 0.f;
#pragma unroll
    for (int i = 0; i < 8; i++) {
        int n = base + ig * 8 + i;
        if (n < N_NODES) C[n * 64 + f] = acc[i] + bv;
    }
}

// ---------------- layer-4 BN apply (inline finalize) -> writes h and h0 ----------------
__global__ __launch_bounds__(256) void bn_apply_final_kernel(
    float* __restrict__ h, float* __restrict__ h0,
    const float* __restrict__ gam, const float* __restrict__ bet)
{
    __shared__ float sc[HID], sh[HID];
    int tid = threadIdx.x;
    if (tid < HID) {
        double mean = g_sum[3][tid] * INV_N;
        double var  = g_sq[3][tid] * INV_N - mean * mean;
        float s = gam[tid] * rsqrtf((float)var + BN_EPS);
        sc[tid] = s;
        sh[tid] = bet[tid] - (float)mean * s;
    }
    __syncthreads();
    int i = blockIdx.x * blockDim.x + tid;
    if (i >= N_NODES * (HID / 4)) return;
    float4 v = ((const float4*)h)[i];
    int f = (i * 4) & (HID - 1);
    v.x = fmaxf(fmaf(v.x, sc[f],     sh[f]),     0.f);
    v.y = fmaxf(fmaf(v.y, sc[f + 1], sh[f + 1]), 0.f);
    v.z = fmaxf(fmaf(v.z, sc[f + 2], sh[f + 2]), 0.f);
    v.w = fmaxf(fmaf(v.w, sc[f + 3], sh[f + 3]), 0.f);
    ((float4*)h)[i]  = v;
    ((float4*)h0)[i] = v;
}

// ---------------- fused FC + log-softmax: out = log_softmax(A @ Wfc + bfc) ----------------
__global__ __launch_bounds__(256) void fc_logsoftmax_kernel(
    const float* __restrict__ A, const float* __restrict__ W,
    const float* __restrict__ bias, float* __restrict__ out)
{
    __shared__ float Ws[64 * 64];
    __shared__ float As[32 * 64];
    __shared__ float L[32][65];
    int tid = threadIdx.x;
    for (int i = tid; i < 64 * 64; i += 256) Ws[i] = W[i];
    int base = blockIdx.x * 32;
    for (int i = tid; i < 32 * 64; i += 256) {
        int r = i >> 6, c = i & 63;
        As[i] = (base + r < N_NODES) ? A[(base + r) * 64 + c] : 0.f;
    }
    __syncthreads();
    int f  = tid & 63;
    int ig = tid >> 6;
    float acc[8];
#pragma unroll
    for (int i = 0; i < 8; i++) acc[i] = 0.f;
#pragma unroll 8
    for (int k = 0; k < 64; k++) {
        float wv = Ws[k * 64 + f];
#pragma unroll
        for (int i = 0; i < 8; i++)
            acc[i] += As[(ig * 8 + i) * 64 + k] * wv;
    }
    float bv = bias[f];
#pragma unroll
    for (int i = 0; i < 8; i++) L[ig * 8 + i][f] = acc[i] + bv;
    __syncthreads();
    // log-softmax: each warp handles 4 rows; 32 lanes cover 64 classes (2 each)
    int w = tid >> 5, lane = tid & 31;
#pragma unroll
    for (int j = 0; j < 4; j++) {
        int r = w * 4 + j;
        int node = base + r;
        if (node >= N_NODES) break;
        float v0 = L[r][lane], v1 = L[r][lane + 32];
        float m = fmaxf(v0, v1);
        for (int o = 16; o; o >>= 1) m = fmaxf(m, __shfl_xor_sync(0xffffffffu, m, o));
        float s = __expf(v0 - m) + __expf(v1 - m);
        for (int o = 16; o; o >>= 1) s += __shfl_xor_sync(0xffffffffu, s, o);
        float ls = m + __logf(s);
        out[node * 64 + lane]      = v0 - ls;
        out[node * 64 + lane + 32] = v1 - ls;
    }
}

// ---------------- host ----------------
extern "C" void kernel_launch(void* const* d_in, const int* in_sizes, int n_in,
                              void* d_out, int out_size) {
    const float* x   = (const float*)d_in[0];
    const void*  ei  = d_in[1];            // int32 or int64, detected on device
    const float* W1  = (const float*)d_in[2];
    const float* b1  = (const float*)d_in[3];
    const float* W2  = (const float*)d_in[4];
    const float* b2  = (const float*)d_in[5];
    const float* Wx  = (const float*)d_in[6];   // [2,64,64]
    const float* bx  = (const float*)d_in[7];   // [2,64]
    const float* g1  = (const float*)d_in[8];
    const float* be1 = (const float*)d_in[9];
    const float* g2  = (const float*)d_in[10];
    const float* be2 = (const float*)d_in[11];
    const float* g3  = (const float*)d_in[12];
    const float* be3 = (const float*)d_in[13];
    const float* Wfc = (const float*)d_in[14];
    const float* bfc = (const float*)d_in[15];
    float* out = (float*)d_out;

    float *hA, *hB, *h0;
    cudaGetSymbolAddress((void**)&hA, g_hA);
    cudaGetSymbolAddress((void**)&hB, g_hB);
    cudaGetSymbolAddress((void**)&h0, g_h0);

    // ---- build normalized CSR (by dst) ----
    init_kernel<<<(N_NODES + 255) / 256, 256>>>((const int*)ei);
    count_deg_kernel<<<(N_EDGES + 255) / 256, 256>>>(ei);
    scan_kernel<<<1, 1024>>>();
    fill_csr_kernel<<<(E2 + 255) / 256, 256>>>(ei);

    const int GEMM_GRID = (N_NODES + 31) / 32;   // 1563
    const int SPMM_GRID = N_NODES / 8;           // 6250

    // ---- layer 1 (IN_F=128, no BN on input) ----
    gemm_kernel<128, -1><<<GEMM_GRID, 256>>>(x, W1, nullptr, hB, nullptr, nullptr);
    spmm_kernel<<<SPMM_GRID, 256>>>(hB, hA, b1, nullptr, 1.f, 0.f);
    bn_stats_kernel<<<256, 256>>>(hA, 0);
    // ---- layer 2 (BN set 0 fused into GEMM input) ----
    gemm_kernel<64, 0><<<GEMM_GRID, 256>>>(hA, W2, nullptr, hB, g1, be1);
    spmm_kernel<<<SPMM_GRID, 256>>>(hB, hA, b2, nullptr, 1.f, 0.f);
    bn_stats_kernel<<<256, 256>>>(hA, 1);
    // ---- extra layer 0 (BN set 1) ----
    gemm_kernel<64, 1><<<GEMM_GRID, 256>>>(hA, Wx, nullptr, hB, g2, be2);
    spmm_kernel<<<SPMM_GRID, 256>>>(hB, hA, bx, nullptr, 1.f, 0.f);
    bn_stats_kernel<<<256, 256>>>(hA, 2);
    // ---- extra layer 1 (BN set 2) ----
    gemm_kernel<64, 2><<<GEMM_GRID, 256>>>(hA, Wx + 64 * 64, nullptr, hB, g3, be3);
    spmm_kernel<<<SPMM_GRID, 256>>>(hB, hA, bx + 64, nullptr, 1.f, 0.f);
    bn_stats_kernel<<<256, 256>>>(hA, 3);
    // ---- final BN apply (set 3) -> hA normalized, h0 copy ----
    bn_apply_final_kernel<<<(N_NODES * (HID / 4) + 255) / 256, 256>>>(hA, h0, g3, be3);

    // ---- APPNP: 10 steps, ping-pong hA <-> hB ----
    float* cur = hA;
    float* nxt = hB;
    for (int it = 0; it < 10; it++) {
        spmm_kernel<<<SPMM_GRID, 256>>>(cur, nxt, nullptr, h0, 0.9f, 0.1f);
        float* t = cur; cur = nxt; nxt = t;
    }
    // result in hA

    // ---- head: FC + log_softmax fused ----
    fc_logsoftmax_kernel<<<GEMM_GRID, 256>>>(cur, Wfc, bfc, out);
}

// round 5
// speedup vs baseline: 1.2702x; 1.1159x over previous
#include <cuda_runtime.h>
#include <cuda_fp16.h>

#define N_NODES 50000
#define N_EDGES 800000
#define E2      850000   // edges + self loops
#define IN_F    128
#define HID     64
#define BN_EPS  1e-5f
#define INV_N   (1.0 / (double)N_NODES)

// ---------------- scratch (device globals; no allocation allowed) ----------------
__device__ int    g_is64;
__device__ int    g_deg[N_NODES];
__device__ int    g_fill[N_NODES];
__device__ float  g_dinv[N_NODES];
__device__ int    g_rowptr[N_NODES + 1];
__device__ __align__(16) int2 g_cw[E2 + 2];   // {col, weight-bits}; padded for int4 tail
__device__ __half g_hA[N_NODES * HID];
__device__ __half g_hB[N_NODES * HID];
__device__ __half g_h0[N_NODES * HID];
__device__ double g_sum[4][HID];
__device__ double g_sq[4][HID];

// ---------------- init: deg=1, fill=0, zero stats, detect edge dtype ----------------
__global__ void init_kernel(const int* __restrict__ e) {
    int n = blockIdx.x * blockDim.x + threadIdx.x;
    if (n < N_NODES) { g_deg[n] = 1; g_fill[n] = 0; }
    if (blockIdx.x == 0) {
        int t = threadIdx.x;
        if (t < 4 * HID) { ((double*)g_sum)[t] = 0.0; ((double*)g_sq)[t] = 0.0; }
        if (t < 32) {
            // int64 little-endian with values < 50000 -> odd 32-bit words all zero
            int nz = 0;
            #pragma unroll
            for (int i = 0; i < 4; i++) nz += (e[2 * (t * 4 + i) + 1] != 0);
            unsigned any = __any_sync(0xffffffffu, nz != 0);
            if (t == 0) g_is64 = any ? 0 : 1;
        }
    }
}

__device__ __forceinline__ int fetch_idx(const void* ei, long long pos) {
    int v;
    if (g_is64) v = (int)((const long long*)ei)[pos];
    else        v = ((const int*)ei)[pos];
    return min(max(v, 0), N_NODES - 1);   // crash insurance
}

__global__ void count_deg_kernel(const void* __restrict__ ei) {
    int e = blockIdx.x * blockDim.x + threadIdx.x;
    if (e < N_EDGES) atomicAdd(&g_deg[fetch_idx(ei, (long long)N_EDGES + e)], 1);
}

// single-block exclusive prefix sum over degrees; also writes dinv
__global__ void scan_kernel() {
    __shared__ int buf[1024];
    const int CH = (N_NODES + 1023) / 1024;  // 49
    int t = threadIdx.x;
    int beg = t * CH;
    int end = min(beg + CH, N_NODES);
    int local = 0;
    for (int i = beg; i < end; i++) {
        int d = g_deg[i];
        g_dinv[i] = rsqrtf((float)d);
        local += d;
    }
    buf[t] = local;
    __syncthreads();
    for (int off = 1; off < 1024; off <<= 1) {
        int add = (t >= off) ? buf[t - off] : 0;
        __syncthreads();
        buf[t] += add;
        __syncthreads();
    }
    int run = buf[t] - local;
    for (int i = beg; i < end; i++) { g_rowptr[i] = run; run += g_deg[i]; }
    if (t == 1023) g_rowptr[N_NODES] = buf[1023];
}

__global__ void fill_csr_kernel(const void* __restrict__ ei) {
    int e = blockIdx.x * blockDim.x + threadIdx.x;
    if (e >= E2) return;
    int s, d;
    if (e < N_EDGES) {
        s = fetch_idx(ei, e);
        d = fetch_idx(ei, (long long)N_EDGES + e);
    } else {
        s = e - N_EDGES; d = s;
    }
    int pos = g_rowptr[d] + atomicAdd(&g_fill[d], 1);
    g_cw[pos] = make_int2(s, __float_as_int(g_dinv[s] * g_dinv[d]));
}

// ---------------- SpMM (fp16 h): warp per node, half2 per lane, fp32 accumulate ----------------
// hout[n] = wacc * sum_e w*hin[col] (+bias) (+wh0*h0[n]); 1 L2 line per edge gather
__global__ __launch_bounds__(256) void spmm_kernel(
    const __half* __restrict__ hin, __half* __restrict__ hout,
    const float* __restrict__ bias, const __half* __restrict__ h0p,
    float wacc, float wh0)
{
    int node = blockIdx.x * 8 + (threadIdx.x >> 5);
    int lane = threadIdx.x & 31;
    const __half2* __restrict__ hin2 = (const __half2*)hin;
    const int4*    __restrict__ cw4  = (const int4*)g_cw;
    int beg = g_rowptr[node];
    int end = g_rowptr[node + 1];
    float2 a0 = make_float2(0.f, 0.f), a1 = a0, a2 = a0, a3 = a0;
    int e = beg;
    if ((e & 1) && e < end) {               // peel to 16B alignment of metadata
        int2 cw = g_cw[e];
        float w = __int_as_float(cw.y);
        float2 v = __half22float2(hin2[cw.x*32 + lane]);
        a0.x += w*v.x; a0.y += w*v.y;
        e++;
    }
    for (; e + 3 < end; e += 4) {
        int4 q0 = cw4[e >> 1];
        int4 q1 = cw4[(e >> 1) + 1];
        float2 v0 = __half22float2(hin2[q0.x*32 + lane]);
        float2 v1 = __half22float2(hin2[q0.z*32 + lane]);
        float2 v2 = __half22float2(hin2[q1.x*32 + lane]);
        float2 v3 = __half22float2(hin2[q1.z*32 + lane]);
        float w0 = __int_as_float(q0.y), w1 = __int_as_float(q0.w);
        float w2 = __int_as_float(q1.y), w3 = __int_as_float(q1.w);
        a0.x += w0*v0.x; a0.y += w0*v0.y;
        a1.x += w1*v1.x; a1.y += w1*v1.y;
        a2.x += w2*v2.x; a2.y += w2*v2.y;
        a3.x += w3*v3.x; a3.y += w3*v3.y;
    }
    for (; e < end; e++) {
        int2 cw = g_cw[e];
        float w = __int_as_float(cw.y);
        float2 v = __half22float2(hin2[cw.x*32 + lane]);
        a0.x += w*v.x; a0.y += w*v.y;
    }
    float2 r;
    r.x = ((a0.x + a1.x) + (a2.x + a3.x)) * wacc;
    r.y = ((a0.y + a1.y) + (a2.y + a3.y)) * wacc;
    if (bias) {
        float2 b = ((const float2*)bias)[lane];
        r.x += b.x; r.y += b.y;
    }
    if (h0p) {
        float2 z = __half22float2(((const __half2*)h0p)[node*32 + lane]);
        r.x += wh0 * z.x; r.y += wh0 * z.y;
    }
    ((__half2*)hout)[node*32 + lane] = __floats2half2_rn(r.x, r.y);
}

// ---------------- BN stats: 256 blocks, float partials, 16k double atomics ----------------
__global__ __launch_bounds__(256) void bn_stats_kernel(const __half* __restrict__ h, int set) {
    int f   = threadIdx.x & 63;
    int grp = threadIdx.x >> 6;  // 0..3
    float s = 0.f, q = 0.f;
    for (int n = blockIdx.x * 4 + grp; n < N_NODES; n += gridDim.x * 4) {
        float v = __half2float(h[n * HID + f]);
        s += v; q += v * v;
    }
    __shared__ float ss[4][HID], qq[4][HID];
    ss[grp][f] = s; qq[grp][f] = q;
    __syncthreads();
    if (grp == 0) {
        s = (ss[0][f] + ss[1][f]) + (ss[2][f] + ss[3][f]);
        q = (qq[0][f] + qq[1][f]) + (qq[2][f] + qq[3][f]);
        atomicAdd(&g_sum[set][f], (double)s);
        atomicAdd(&g_sq[set][f],  (double)q);
    }
}

// ---------------- dense GEMM with optional fused BN(+ReLU) on the input ----------------
// C[N,64] = act(A)[N,KIN] @ W[KIN,64] (+bias); act = BN(scale,shift)+ReLU when BNSET>=0
// TA = float (layer 1 input x) or __half (hidden state)
template <int KIN, int BNSET, typename TA>
__global__ __launch_bounds__(256) void gemm_kernel(
    const TA* __restrict__ A, const float* __restrict__ W,
    const float* __restrict__ bias, __half* __restrict__ C,
    const float* __restrict__ gam, const float* __restrict__ bet)
{
    __shared__ float Ws[KIN * 64];
    __shared__ float As[32 * KIN];
    __shared__ float sc[HID], sh[HID];
    int tid = threadIdx.x;
    if (BNSET >= 0 && tid < HID) {
        double mean = g_sum[BNSET][tid] * INV_N;
        double var  = g_sq[BNSET][tid] * INV_N - mean * mean;
        float s = gam[tid] * rsqrtf((float)var + BN_EPS);
        sc[tid] = s;
        sh[tid] = bet[tid] - (float)mean * s;
    }
    for (int i = tid; i < KIN * 64; i += 256) Ws[i] = W[i];
    if (BNSET >= 0) __syncthreads();   // sc/sh ready before A-load uses them
    int base = blockIdx.x * 32;
    // load 2 elements per thread-step (coalesced pairs)
    for (int i = tid; i < 32 * (KIN / 2); i += 256) {
        int r = i / (KIN / 2), c = (i - r * (KIN / 2)) * 2;
        float v0 = 0.f, v1 = 0.f;
        if (base + r < N_NODES) {
            if constexpr (sizeof(TA) == 2) {
                float2 p = __half22float2(((const __half2*)A)[((base + r) * KIN + c) >> 1]);
                v0 = p.x; v1 = p.y;
            } else {
                float2 p = ((const float2*)A)[((base + r) * KIN + c) >> 1];
                v0 = p.x; v1 = p.y;
            }
        }
        if (BNSET >= 0) {
            v0 = fmaxf(fmaf(v0, sc[c],     sh[c]),     0.f);
            v1 = fmaxf(fmaf(v1, sc[c + 1], sh[c + 1]), 0.f);
        }
        As[r * KIN + c]     = v0;
        As[r * KIN + c + 1] = v1;
    }
    __syncthreads();
    int f  = tid & 63;
    int ig = tid >> 6;
    float acc[8];
#pragma unroll
    for (int i = 0; i < 8; i++) acc[i] = 0.f;
#pragma unroll 8
    for (int k = 0; k < KIN; k++) {
        float wv = Ws[k * 64 + f];
#pragma unroll
        for (int i = 0; i < 8; i++)
            acc[i] += As[(ig * 8 + i) * KIN + k] * wv;
    }
    float bv = bias ? bias[f] : 0.f;
#pragma unroll
    for (int i = 0; i < 8; i++) {
        int n = base + ig * 8 + i;
        if (n < N_NODES) C[n * 64 + f] = __float2half(acc[i] + bv);
    }
}

// ---------------- layer-4 BN apply (inline finalize) -> writes h and h0 (fp16) ----------------
__global__ __launch_bounds__(256) void bn_apply_final_kernel(
    __half* __restrict__ h, __half* __restrict__ h0,
    const float* __restrict__ gam, const float* __restrict__ bet)
{
    __shared__ float sc[HID], sh[HID];
    int tid = threadIdx.x;
    if (tid < HID) {
        double mean = g_sum[3][tid] * INV_N;
        double var  = g_sq[3][tid] * INV_N - mean * mean;
        float s = gam[tid] * rsqrtf((float)var + BN_EPS);
        sc[tid] = s;
        sh[tid] = bet[tid] - (float)mean * s;
    }
    __syncthreads();
    int i = blockIdx.x * blockDim.x + tid;   // over N*32 half2s (exact)
    float2 v = __half22float2(((const __half2*)h)[i]);
    int f = (i * 2) & (HID - 1);
    v.x = fmaxf(fmaf(v.x, sc[f],     sh[f]),     0.f);
    v.y = fmaxf(fmaf(v.y, sc[f + 1], sh[f + 1]), 0.f);
    __half2 o = __floats2half2_rn(v.x, v.y);
    ((__half2*)h)[i]  = o;
    ((__half2*)h0)[i] = o;
}

// ---------------- fused FC + log-softmax: out = log_softmax(A @ Wfc + bfc) ----------------
__global__ __launch_bounds__(256) void fc_logsoftmax_kernel(
    const __half* __restrict__ A, const float* __restrict__ W,
    const float* __restrict__ bias, float* __restrict__ out)
{
    __shared__ float Ws[64 * 64];
    __shared__ float As[32 * 64];
    __shared__ float L[32][65];
    int tid = threadIdx.x;
    for (int i = tid; i < 64 * 64; i += 256) Ws[i] = W[i];
    int base = blockIdx.x * 32;
    for (int i = tid; i < 32 * 32; i += 256) {     // half2 pairs
        int r = i >> 4, c = (i & 15) * 2;          // wrong split? 32 cols of pairs
        // recompute: 64 features = 32 half2 per row; idx i over 32 rows * 32 pairs
        r = i / 32; c = (i - r * 32) * 2;
        float2 p = make_float2(0.f, 0.f);
        if (base + r < N_NODES)
            p = __half22float2(((const __half2*)A)[((base + r) * 64 + c) >> 1]);
        As[r * 64 + c]     = p.x;
        As[r * 64 + c + 1] = p.y;
    }
    __syncthreads();
    int f  = tid & 63;
    int ig = tid >> 6;
    float acc[8];
#pragma unroll
    for (int i = 0; i < 8; i++) acc[i] = 0.f;
#pragma unroll 8
    for (int k = 0; k < 64; k++) {
        float wv = Ws[k * 64 + f];
#pragma unroll
        for (int i = 0; i < 8; i++)
            acc[i] += As[(ig * 8 + i) * 64 + k] * wv;
    }
    float bv = bias[f];
#pragma unroll
    for (int i = 0; i < 8; i++) L[ig * 8 + i][f] = acc[i] + bv;
    __syncthreads();
    // log-softmax: each warp handles 4 rows; 32 lanes cover 64 classes (2 each)
    int w = tid >> 5, lane = tid & 31;
#pragma unroll
    for (int j = 0; j < 4; j++) {
        int r = w * 4 + j;
        int node = base + r;
        if (node >= N_NODES) break;
        float v0 = L[r][lane], v1 = L[r][lane + 32];
        float m = fmaxf(v0, v1);
        for (int o = 16; o; o >>= 1) m = fmaxf(m, __shfl_xor_sync(0xffffffffu, m, o));
        float s = __expf(v0 - m) + __expf(v1 - m);
        for (int o = 16; o; o >>= 1) s += __shfl_xor_sync(0xffffffffu, s, o);
        float ls = m + __logf(s);
        out[node * 64 + lane]      = v0 - ls;
        out[node * 64 + lane + 32] = v1 - ls;
    }
}

// ---------------- host ----------------
extern "C" void kernel_launch(void* const* d_in, const int* in_sizes, int n_in,
                              void* d_out, int out_size) {
    const float* x   = (const float*)d_in[0];
    const void*  ei  = d_in[1];            // int32 or int64, detected on device
    const float* W1  = (const float*)d_in[2];
    const float* b1  = (const float*)d_in[3];
    const float* W2  = (const float*)d_in[4];
    const float* b2  = (const float*)d_in[5];
    const float* Wx  = (const float*)d_in[6];   // [2,64,64]
    const float* bx  = (const float*)d_in[7];   // [2,64]
    const float* g1  = (const float*)d_in[8];
    const float* be1 = (const float*)d_in[9];
    const float* g2  = (const float*)d_in[10];
    const float* be2 = (const float*)d_in[11];
    const float* g3  = (const float*)d_in[12];
    const float* be3 = (const float*)d_in[13];
    const float* Wfc = (const float*)d_in[14];
    const float* bfc = (const float*)d_in[15];
    float* out = (float*)d_out;

    __half *hA, *hB, *h0;
    cudaGetSymbolAddress((void**)&hA, g_hA);
    cudaGetSymbolAddress((void**)&hB, g_hB);
    cudaGetSymbolAddress((void**)&h0, g_h0);

    // ---- build normalized CSR (by dst) ----
    init_kernel<<<(N_NODES + 255) / 256, 256>>>((const int*)ei);
    count_deg_kernel<<<(N_EDGES + 255) / 256, 256>>>(ei);
    scan_kernel<<<1, 1024>>>();
    fill_csr_kernel<<<(E2 + 255) / 256, 256>>>(ei);

    const int GEMM_GRID = (N_NODES + 31) / 32;   // 1563
    const int SPMM_GRID = N_NODES / 8;           // 6250

    // ---- layer 1 (IN_F=128 fp32 input, no BN) ----
    gemm_kernel<128, -1, float><<<GEMM_GRID, 256>>>(x, W1, nullptr, hB, nullptr, nullptr);
    spmm_kernel<<<SPMM_GRID, 256>>>(hB, hA, b1, nullptr, 1.f, 0.f);
    bn_stats_kernel<<<256, 256>>>(hA, 0);
    // ---- layer 2 (BN set 0 fused into GEMM input) ----
    gemm_kernel<64, 0, __half><<<GEMM_GRID, 256>>>(hA, W2, nullptr, hB, g1, be1);
    spmm_kernel<<<SPMM_GRID, 256>>>(hB, hA, b2, nullptr, 1.f, 0.f);
    bn_stats_kernel<<<256, 256>>>(hA, 1);
    // ---- extra layer 0 (BN set 1) ----
    gemm_kernel<64, 1, __half><<<GEMM_GRID, 256>>>(hA, Wx, nullptr, hB, g2, be2);
    spmm_kernel<<<SPMM_GRID, 256>>>(hB, hA, bx, nullptr, 1.f, 0.f);
    bn_stats_kernel<<<256, 256>>>(hA, 2);
    // ---- extra layer 1 (BN set 2) ----
    gemm_kernel<64, 2, __half><<<GEMM_GRID, 256>>>(hA, Wx + 64 * 64, nullptr, hB, g3, be3);
    spmm_kernel<<<SPMM_GRID, 256>>>(hB, hA, bx + 64, nullptr, 1.f, 0.f);
    bn_stats_kernel<<<256, 256>>>(hA, 3);
    // ---- final BN apply (set 3) -> hA normalized, h0 copy ----
    bn_apply_final_kernel<<<(N_NODES * 32) / 256, 256>>>(hA, h0, g3, be3);

    // ---- APPNP: 10 steps, ping-pong hA <-> hB ----
    __half* cur = hA;
    __half* nxt = hB;
    for (int it = 0; it < 10; it++) {
        spmm_kernel<<<SPMM_GRID, 256>>>(cur, nxt, nullptr, h0, 0.9f, 0.1f);
        __half* t = cur; cur = nxt; nxt = t;
    }
    // result in hA

    // ---- head: FC + log_softmax fused ----
    fc_logsoftmax_kernel<<<GEMM_GRID, 256>>>(cur, Wfc, bfc, out);
}